// round 4
// baseline (speedup 1.0000x reference)
#include <cuda_runtime.h>
#include <cuda_fp16.h>
#include <cstdint>

#define B_   128
#define N_   512
#define FIN  128
#define FOUT 64

// Scratch (allocation-free rule: __device__ globals)
__device__ __half g_hh[B_ * N_ * FOUT];   // h hi part fp16, row-major [row][f]
__device__ __half g_hl[B_ * N_ * FOUT];   // h lo part fp16
__device__ float  g_s[B_ * N_];
__device__ float  g_t[B_ * N_];

// ---------------------------------------------------------------------------
// PTX helpers
// ---------------------------------------------------------------------------
__device__ __forceinline__ uint32_t smem_u32(const void* p) {
    return (uint32_t)__cvta_generic_to_shared(p);
}
__device__ __forceinline__ void ldsm_x4(uint32_t& r0, uint32_t& r1, uint32_t& r2, uint32_t& r3, uint32_t addr) {
    asm volatile("ldmatrix.sync.aligned.m8n8.x4.shared.b16 {%0,%1,%2,%3}, [%4];\n"
                 : "=r"(r0), "=r"(r1), "=r"(r2), "=r"(r3) : "r"(addr));
}
__device__ __forceinline__ void ldsm_x4t(uint32_t& r0, uint32_t& r1, uint32_t& r2, uint32_t& r3, uint32_t addr) {
    asm volatile("ldmatrix.sync.aligned.m8n8.x4.trans.shared.b16 {%0,%1,%2,%3}, [%4];\n"
                 : "=r"(r0), "=r"(r1), "=r"(r2), "=r"(r3) : "r"(addr));
}
__device__ __forceinline__ void mma16816(float* d, uint32_t a0, uint32_t a1, uint32_t a2, uint32_t a3,
                                         uint32_t b0, uint32_t b1) {
    asm volatile("mma.sync.aligned.m16n8k16.row.col.f32.f16.f16.f32 "
                 "{%0,%1,%2,%3},{%4,%5,%6,%7},{%8,%9},{%0,%1,%2,%3};\n"
                 : "+f"(d[0]), "+f"(d[1]), "+f"(d[2]), "+f"(d[3])
                 : "r"(a0), "r"(a1), "r"(a2), "r"(a3), "r"(b0), "r"(b1));
}

// ---------------------------------------------------------------------------
// Kernel A: h = X @ W  (M=65536, K=128, N=64), K split in 2 halves for occ.
//   writes fp16 hi/lo split of h, and fused s = h.a_src, t = h.a_dst
// ---------------------------------------------------------------------------
__global__ void __launch_bounds__(256) gemm1_kernel(
    const float* __restrict__ X, const float* __restrict__ W,
    const float* __restrict__ a)
{
    extern __shared__ float sm[];
    float* Xs = sm;               // [64][68]  (one K-half)
    float* Ws = sm + 64 * 68;     // [128][64] (full W)

    const int tid = threadIdx.x;
    const int m0  = blockIdx.x * 64;

    // Load full W 128x64 once
#pragma unroll
    for (int p = 0; p < 8; p++) {
        int u  = p * 256 + tid;
        int k  = u >> 4;
        int c4 = (u & 15) * 4;
        *(float4*)(Ws + k * 64 + c4) = *(const float4*)(W + k * 64 + c4);
    }

    const int tx = tid & 15;
    const int ty = tid >> 4;
    float acc[4][4] = {};

#pragma unroll
    for (int kh = 0; kh < 2; kh++) {
        // Load X half-tile 64x64
#pragma unroll
        for (int p = 0; p < 4; p++) {
            int u  = p * 256 + tid;
            int r  = u >> 4;
            int k4 = (u & 15) * 4;
            *(float4*)(Xs + r * 68 + k4) =
                *(const float4*)(X + (size_t)(m0 + r) * FIN + kh * 64 + k4);
        }
        __syncthreads();

#pragma unroll 8
        for (int k = 0; k < 64; k++) {
            float4 wv = *(const float4*)(Ws + (kh * 64 + k) * 64 + tx * 4);
            float x0 = Xs[(ty * 4 + 0) * 68 + k];
            float x1 = Xs[(ty * 4 + 1) * 68 + k];
            float x2 = Xs[(ty * 4 + 2) * 68 + k];
            float x3 = Xs[(ty * 4 + 3) * 68 + k];
            acc[0][0] += x0 * wv.x; acc[0][1] += x0 * wv.y; acc[0][2] += x0 * wv.z; acc[0][3] += x0 * wv.w;
            acc[1][0] += x1 * wv.x; acc[1][1] += x1 * wv.y; acc[1][2] += x1 * wv.z; acc[1][3] += x1 * wv.w;
            acc[2][0] += x2 * wv.x; acc[2][1] += x2 * wv.y; acc[2][2] += x2 * wv.z; acc[2][3] += x2 * wv.w;
            acc[3][0] += x3 * wv.x; acc[3][1] += x3 * wv.y; acc[3][2] += x3 * wv.z; acc[3][3] += x3 * wv.w;
        }
        __syncthreads();
    }

    // a_src / a_dst slices for this thread's 4 columns
    float as[4], ad[4];
#pragma unroll
    for (int c = 0; c < 4; c++) {
        as[c] = __ldg(a + tx * 4 + c);
        ad[c] = __ldg(a + 64 + tx * 4 + c);
    }

#pragma unroll
    for (int i = 0; i < 4; i++) {
        size_t row = (size_t)(m0 + ty * 4 + i);
        __half hi[4], lo[4];
#pragma unroll
        for (int c = 0; c < 4; c++) {
            hi[c] = __float2half(acc[i][c]);
            lo[c] = __float2half(acc[i][c] - __half2float(hi[c]));
        }
        *(uint2*)(g_hh + row * FOUT + tx * 4) = *(uint2*)hi;
        *(uint2*)(g_hl + row * FOUT + tx * 4) = *(uint2*)lo;

        float sp = acc[i][0] * as[0] + acc[i][1] * as[1] + acc[i][2] * as[2] + acc[i][3] * as[3];
        float tp = acc[i][0] * ad[0] + acc[i][1] * ad[1] + acc[i][2] * ad[2] + acc[i][3] * ad[3];
#pragma unroll
        for (int o = 8; o; o >>= 1) {
            sp += __shfl_xor_sync(0xffffffffu, sp, o);
            tp += __shfl_xor_sync(0xffffffffu, tp, o);
        }
        if (tx == 0) { g_s[row] = sp; g_t[row] = tp; }
    }
}

// ---------------------------------------------------------------------------
// Kernel B: fused masked-softmax (factorized exp) + tensor-core att@h + lrelu
// Block = (32-row tile, batch). 256 threads = 8 warps.
// ---------------------------------------------------------------------------
#define ATT_S 520   // fp16 stride for att rows (512 + 8 pad)
#define HS_S  72    // fp16 stride for h chunk rows (64 + 8 pad)

__global__ void __launch_bounds__(256) attn_kernel(
    const int* __restrict__ adj, float* __restrict__ out)
{
    extern __shared__ char smraw[];
    float4* tE4 = (float4*)smraw;                    // 512 x float4 (swizzled) = 8KB
    float* inv  = (float*)(tE4 + 512);               // 32
    float* wmax = inv + 32;                          // 8
    __half* attF = (__half*)(wmax + 8);              // 32 x 520
    __half* hsHi = attF + 32 * ATT_S;                // 64 x 72
    __half* hsLo = hsHi + 64 * HS_S;                 // 64 x 72

    const int b    = blockIdx.y;
    const int r0   = blockIdx.x * 32;
    const int tid  = threadIdx.x;
    const int warp = tid >> 5;
    const int lane = tid & 31;

    float t0 = g_t[b * N_ + tid];
    float t1 = g_t[b * N_ + tid + 256];

    // block max of t (softmax shift via monotonicity of leaky)
    float m2 = fmaxf(t0, t1);
#pragma unroll
    for (int o = 16; o; o >>= 1) m2 = fmaxf(m2, __shfl_xor_sync(0xffffffffu, m2, o));
    if (lane == 0) wmax[warp] = m2;
    __syncthreads();
    const float maxT = fmaxf(fmaxf(fmaxf(wmax[0], wmax[1]), fmaxf(wmax[2], wmax[3])),
                             fmaxf(fmaxf(wmax[4], wmax[5]), fmaxf(wmax[6], wmax[7])));

    // Build swizzled table: tE4[(j&3)*128 + (j>>2)] = (t_j, exp(t_j-maxT), exp(0.2(t_j-maxT)), 0)
    {
        float d0 = t0 - maxT, d1 = t1 - maxT;
        int j0 = tid, j1 = tid + 256;
        tE4[(j0 & 3) * 128 + (j0 >> 2)] = make_float4(t0, __expf(d0), __expf(0.2f * d0), 0.f);
        tE4[(j1 & 3) * 128 + (j1 >> 2)] = make_float4(t1, __expf(d1), __expf(0.2f * d1), 0.f);
    }
    __syncthreads();

    // ---- Phase 1: masked factorized softmax weights (fp16, unnormalized) ----
#pragma unroll
    for (int rr = 0; rr < 4; rr++) {
        int r    = warp * 4 + rr;
        int grow = r0 + r;
        float s  = g_s[b * N_ + grow];
        float pm = s + maxT;
        float mx = pm > 0.f ? pm : 0.2f * pm;        // true row max of leaky logits
        float f1 = __expf(pm - mx);                  // pos-branch row factor (<=1)
        float f2 = __expf(0.2f * pm - mx);           // neg-branch row factor (<=1)
        const int4* arow = (const int4*)(adj + ((size_t)b * N_ + grow) * N_);

        float sum = 0.f;
#pragma unroll
        for (int it = 0; it < 4; it++) {
            int4 av = arow[it * 32 + lane];
            int jq  = it * 32 + lane;                // = j>>2 for this lane's 4 elems
            float w[4];
#pragma unroll
            for (int c = 0; c < 4; c++) {
                float4 te = tE4[c * 128 + jq];       // conflict-free: 16B-stride across lanes
                float wv = (s + te.x > 0.f) ? f1 * te.y : f2 * te.z;
                w[c] = ((&av.x)[c] > 0) ? wv : 0.f;
                sum += w[c];
            }
            __half2 p0 = __floats2half2_rn(w[0], w[1]);
            __half2 p1 = __floats2half2_rn(w[2], w[3]);
            *(uint2*)(attF + r * ATT_S + it * 128 + lane * 4) =
                make_uint2(*(uint32_t*)&p0, *(uint32_t*)&p1);
        }
#pragma unroll
        for (int o = 16; o; o >>= 1) sum += __shfl_xor_sync(0xffffffffu, sum, o);
        if (lane == 0) inv[r] = 1.0f / sum;
    }
    __syncthreads();

    // ---- Phase 2: C[32,64] = att @ h[b]  via mma.m16n8k16.f16 (2-term h split) ----
    const int mtile = warp >> 2;
    const int ntg0  = (warp & 3) * 2;
    const int lrow16 = lane & 15;

    uint32_t aAddr  = smem_u32(attF + (mtile * 16 + lrow16) * ATT_S + (lane >> 4) * 8);
    uint32_t bAddrH = smem_u32(hsHi + lrow16 * HS_S + (ntg0 + (lane >> 4)) * 8);
    uint32_t bAddrL = smem_u32(hsLo + lrow16 * HS_S + (ntg0 + (lane >> 4)) * 8);

    float acc0[4] = {0.f, 0.f, 0.f, 0.f};
    float acc1[4] = {0.f, 0.f, 0.f, 0.f};

    const __half* hbHi = g_hh + (size_t)b * N_ * FOUT;
    const __half* hbLo = g_hl + (size_t)b * N_ * FOUT;

    for (int c = 0; c < 8; c++) {
        const int k0 = c * 64;
#pragma unroll
        for (int rep = 0; rep < 2; rep++) {
            int u   = rep * 256 + tid;
            int row = u >> 3;
            int off = (u & 7) * 8;
            *(uint4*)(hsHi + row * HS_S + off) = *(const uint4*)(hbHi + (size_t)(k0 + row) * FOUT + off);
            *(uint4*)(hsLo + row * HS_S + off) = *(const uint4*)(hbLo + (size_t)(k0 + row) * FOUT + off);
        }
        __syncthreads();

#pragma unroll
        for (int ks = 0; ks < 4; ks++) {
            const uint32_t aOff = (uint32_t)(k0 + ks * 16) * 2;
            const uint32_t bOff = (uint32_t)(ks * 16) * HS_S * 2;

            uint32_t a0, a1, a2, a3;
            ldsm_x4(a0, a1, a2, a3, aAddr + aOff);

            uint32_t bh0, bh1, bh2, bh3, bl0, bl1, bl2, bl3;
            ldsm_x4t(bh0, bh1, bh2, bh3, bAddrH + bOff);
            ldsm_x4t(bl0, bl1, bl2, bl3, bAddrL + bOff);

            mma16816(acc0, a0, a1, a2, a3, bh0, bh1);
            mma16816(acc0, a0, a1, a2, a3, bl0, bl1);
            mma16816(acc1, a0, a1, a2, a3, bh2, bh3);
            mma16816(acc1, a0, a1, a2, a3, bl2, bl3);
        }
        __syncthreads();
    }

    // ---- Epilogue: normalize + leaky_relu(0.01) + store ----
    const int gid = lane >> 2;
    const int tg  = lane & 3;
    const int rA  = mtile * 16 + gid;
    const int rB  = rA + 8;
    const float invA = inv[rA];
    const float invB = inv[rB];

#pragma unroll
    for (int nt = 0; nt < 2; nt++) {
        float* acc = nt ? acc1 : acc0;
        int col = (ntg0 + nt) * 8 + tg * 2;
        float v;
        float2 oA, oB;
        v = acc[0] * invA; oA.x = v > 0.f ? v : 0.01f * v;
        v = acc[1] * invA; oA.y = v > 0.f ? v : 0.01f * v;
        v = acc[2] * invB; oB.x = v > 0.f ? v : 0.01f * v;
        v = acc[3] * invB; oB.y = v > 0.f ? v : 0.01f * v;
        *(float2*)(out + ((size_t)b * N_ + r0 + rA) * FOUT + col) = oA;
        *(float2*)(out + ((size_t)b * N_ + r0 + rB) * FOUT + col) = oB;
    }
}

// ---------------------------------------------------------------------------
extern "C" void kernel_launch(void* const* d_in, const int* in_sizes, int n_in,
                              void* d_out, int out_size)
{
    const float* X   = (const float*)d_in[0];
    const int*   adj = (const int*)  d_in[1];
    const float* W   = (const float*)d_in[2];
    const float* a   = (const float*)d_in[3];
    float* out = (float*)d_out;

    size_t smA = (size_t)(64 * 68 + 128 * 64) * sizeof(float);   // ~50 KB -> 4 blocks/SM
    cudaFuncSetAttribute(gemm1_kernel, cudaFuncAttributeMaxDynamicSharedMemorySize, (int)smA);
    gemm1_kernel<<<(B_ * N_) / 64, 256, smA>>>(X, W, a);

    size_t smB = 512 * sizeof(float4) + (32 + 8) * sizeof(float)
               + (size_t)(32 * ATT_S + 2 * 64 * HS_S) * sizeof(__half);
    cudaFuncSetAttribute(attn_kernel, cudaFuncAttributeMaxDynamicSharedMemorySize, (int)smB);
    attn_kernel<<<dim3(N_ / 32, B_), 256, smB>>>(adj, out);
}

// round 5
// speedup vs baseline: 1.2242x; 1.2242x over previous
#include <cuda_runtime.h>
#include <cuda_fp16.h>
#include <cstdint>

#define B_   128
#define N_   512
#define FIN  128
#define FOUT 64

// Scratch (allocation-free rule: __device__ globals)
__device__ __half g_hh[B_ * N_ * FOUT];   // h fp16, row-major [row][f]
__device__ float  g_s[B_ * N_];
__device__ float  g_t[B_ * N_];

// ---------------------------------------------------------------------------
// PTX helpers
// ---------------------------------------------------------------------------
__device__ __forceinline__ uint32_t smem_u32(const void* p) {
    return (uint32_t)__cvta_generic_to_shared(p);
}
__device__ __forceinline__ void ldsm_x4(uint32_t& r0, uint32_t& r1, uint32_t& r2, uint32_t& r3, uint32_t addr) {
    asm volatile("ldmatrix.sync.aligned.m8n8.x4.shared.b16 {%0,%1,%2,%3}, [%4];\n"
                 : "=r"(r0), "=r"(r1), "=r"(r2), "=r"(r3) : "r"(addr));
}
__device__ __forceinline__ void ldsm_x4t(uint32_t& r0, uint32_t& r1, uint32_t& r2, uint32_t& r3, uint32_t addr) {
    asm volatile("ldmatrix.sync.aligned.m8n8.x4.trans.shared.b16 {%0,%1,%2,%3}, [%4];\n"
                 : "=r"(r0), "=r"(r1), "=r"(r2), "=r"(r3) : "r"(addr));
}
__device__ __forceinline__ void mma16816(float* d, uint32_t a0, uint32_t a1, uint32_t a2, uint32_t a3,
                                         uint32_t b0, uint32_t b1) {
    asm volatile("mma.sync.aligned.m16n8k16.row.col.f32.f16.f16.f32 "
                 "{%0,%1,%2,%3},{%4,%5,%6,%7},{%8,%9},{%0,%1,%2,%3};\n"
                 : "+f"(d[0]), "+f"(d[1]), "+f"(d[2]), "+f"(d[3])
                 : "r"(a0), "r"(a1), "r"(a2), "r"(a3), "r"(b0), "r"(b1));
}

// ---------------------------------------------------------------------------
// Kernel A: h = X @ W  (M=65536, K=128, N=64), K split in 2 halves for occ.
//   writes fp16 h, and fused s = h.a_src, t = h.a_dst
// ---------------------------------------------------------------------------
__global__ void __launch_bounds__(256) gemm1_kernel(
    const float* __restrict__ X, const float* __restrict__ W,
    const float* __restrict__ a)
{
    extern __shared__ float sm[];
    float* Xs = sm;               // [64][68]  (one K-half)
    float* Ws = sm + 64 * 68;     // [128][64] (full W)

    const int tid = threadIdx.x;
    const int m0  = blockIdx.x * 64;

#pragma unroll
    for (int p = 0; p < 8; p++) {
        int u  = p * 256 + tid;
        int k  = u >> 4;
        int c4 = (u & 15) * 4;
        *(float4*)(Ws + k * 64 + c4) = *(const float4*)(W + k * 64 + c4);
    }

    const int tx = tid & 15;
    const int ty = tid >> 4;
    float acc[4][4] = {};

#pragma unroll
    for (int kh = 0; kh < 2; kh++) {
#pragma unroll
        for (int p = 0; p < 4; p++) {
            int u  = p * 256 + tid;
            int r  = u >> 4;
            int k4 = (u & 15) * 4;
            *(float4*)(Xs + r * 68 + k4) =
                *(const float4*)(X + (size_t)(m0 + r) * FIN + kh * 64 + k4);
        }
        __syncthreads();

#pragma unroll 8
        for (int k = 0; k < 64; k++) {
            float4 wv = *(const float4*)(Ws + (kh * 64 + k) * 64 + tx * 4);
            float x0 = Xs[(ty * 4 + 0) * 68 + k];
            float x1 = Xs[(ty * 4 + 1) * 68 + k];
            float x2 = Xs[(ty * 4 + 2) * 68 + k];
            float x3 = Xs[(ty * 4 + 3) * 68 + k];
            acc[0][0] += x0 * wv.x; acc[0][1] += x0 * wv.y; acc[0][2] += x0 * wv.z; acc[0][3] += x0 * wv.w;
            acc[1][0] += x1 * wv.x; acc[1][1] += x1 * wv.y; acc[1][2] += x1 * wv.z; acc[1][3] += x1 * wv.w;
            acc[2][0] += x2 * wv.x; acc[2][1] += x2 * wv.y; acc[2][2] += x2 * wv.z; acc[2][3] += x2 * wv.w;
            acc[3][0] += x3 * wv.x; acc[3][1] += x3 * wv.y; acc[3][2] += x3 * wv.z; acc[3][3] += x3 * wv.w;
        }
        __syncthreads();
    }

    float as[4], ad[4];
#pragma unroll
    for (int c = 0; c < 4; c++) {
        as[c] = __ldg(a + tx * 4 + c);
        ad[c] = __ldg(a + 64 + tx * 4 + c);
    }

#pragma unroll
    for (int i = 0; i < 4; i++) {
        size_t row = (size_t)(m0 + ty * 4 + i);
        __half hv[4];
#pragma unroll
        for (int c = 0; c < 4; c++) hv[c] = __float2half(acc[i][c]);
        *(uint2*)(g_hh + row * FOUT + tx * 4) = *(uint2*)hv;

        float sp = acc[i][0] * as[0] + acc[i][1] * as[1] + acc[i][2] * as[2] + acc[i][3] * as[3];
        float tp = acc[i][0] * ad[0] + acc[i][1] * ad[1] + acc[i][2] * ad[2] + acc[i][3] * ad[3];
#pragma unroll
        for (int o = 8; o; o >>= 1) {
            sp += __shfl_xor_sync(0xffffffffu, sp, o);
            tp += __shfl_xor_sync(0xffffffffu, tp, o);
        }
        if (tx == 0) { g_s[row] = sp; g_t[row] = tp; }
    }
}

// ---------------------------------------------------------------------------
// Kernel B: chunked fused masked-softmax + tensor-core att@h + lrelu
// Block = (32-row tile, batch). 256 threads = 8 warps. smem ~16 KB.
// Per 64-col chunk: compute fp16 weights -> smem, immediately MMA into f32 acc.
// Exact softmax shift via monotonicity: mx_r = leaky(s_r + max_j t_j).
// ---------------------------------------------------------------------------
#define ATT_S 72    // fp16 stride (64 + 8 pad)
#define HS_S  72

__global__ void __launch_bounds__(256, 5) attn_kernel(
    const int* __restrict__ adj, float* __restrict__ out)
{
    extern __shared__ char smraw[];
    float* t_sh = (float*)smraw;                 // 512
    float* inv  = t_sh + 512;                    // 32
    float* wmax = inv + 32;                      // 8
    __half* attC = (__half*)(wmax + 8);          // 32 x 72
    __half* hsC  = attC + 32 * ATT_S;            // 64 x 72

    const int b    = blockIdx.y;
    const int r0   = blockIdx.x * 32;
    const int tid  = threadIdx.x;
    const int warp = tid >> 5;
    const int lane = tid & 31;

    float t0 = g_t[b * N_ + tid];
    float t1 = g_t[b * N_ + tid + 256];
    t_sh[tid]       = t0;
    t_sh[tid + 256] = t1;

    float m2 = fmaxf(t0, t1);
#pragma unroll
    for (int o = 16; o; o >>= 1) m2 = fmaxf(m2, __shfl_xor_sync(0xffffffffu, m2, o));
    if (lane == 0) wmax[warp] = m2;
    __syncthreads();
    const float maxT = fmaxf(fmaxf(fmaxf(wmax[0], wmax[1]), fmaxf(wmax[2], wmax[3])),
                             fmaxf(fmaxf(wmax[4], wmax[5]), fmaxf(wmax[6], wmax[7])));

    // Per-row constants (each warp owns local rows warp*4 .. warp*4+3)
    float s_r[4], mx_r[4], sum_r[4];
#pragma unroll
    for (int rr = 0; rr < 4; rr++) {
        int grow = r0 + warp * 4 + rr;
        float s  = g_s[b * N_ + grow];
        float pm = s + maxT;
        s_r[rr]  = s;
        mx_r[rr] = pm > 0.f ? pm : 0.2f * pm;   // exact max_j leaky(s + t_j)
        sum_r[rr] = 0.f;
    }

    // ldmatrix fragment addresses
    const int mtile  = warp >> 2;           // 0..1
    const int ntg0   = (warp & 3) * 2;      // n8 tile pair
    const int lrow16 = lane & 15;
    const int lhalf  = lane >> 4;
    const uint32_t aAddr = smem_u32(attC + (mtile * 16 + lrow16) * ATT_S + lhalf * 8);
    const uint32_t bAddr = smem_u32(hsC + lrow16 * HS_S + (ntg0 + lhalf) * 8);

    float acc0[4] = {0.f, 0.f, 0.f, 0.f};
    float acc1[4] = {0.f, 0.f, 0.f, 0.f};

    const __half* hb = g_hh + (size_t)b * N_ * FOUT;
    const int* adjB  = adj + ((size_t)b * N_ + r0) * N_;

    for (int c = 0; c < 8; c++) {
        const int k0 = c * 64;

        // load h chunk [64 k-rows][64 f] fp16
#pragma unroll
        for (int rep = 0; rep < 2; rep++) {
            int u   = rep * 256 + tid;
            int row = u >> 3;
            int off = (u & 7) * 8;
            *(uint4*)(hsC + row * HS_S + off) =
                *(const uint4*)(hb + (size_t)(k0 + row) * FOUT + off);
        }

        // phase-1 chunk: weights for 32 rows x 64 cols
#pragma unroll
        for (int rr = 0; rr < 4; rr++) {
            int r = warp * 4 + rr;
            int2 av = *(const int2*)(adjB + (size_t)r * N_ + k0 + lane * 2);
            float2 tv = *(const float2*)(t_sh + k0 + lane * 2);
            float e0 = s_r[rr] + tv.x; e0 = e0 > 0.f ? e0 : 0.2f * e0;
            float e1 = s_r[rr] + tv.y; e1 = e1 > 0.f ? e1 : 0.2f * e1;
            float w0 = av.x > 0 ? __expf(e0 - mx_r[rr]) : 0.f;
            float w1 = av.y > 0 ? __expf(e1 - mx_r[rr]) : 0.f;
            sum_r[rr] += w0 + w1;
            __half2 p = __floats2half2_rn(w0, w1);
            *(uint32_t*)(attC + r * ATT_S + lane * 2) = *(uint32_t*)&p;
        }
        __syncthreads();

        // MMA: C[32,64] += attC[32,64] @ hsC[64,64]
#pragma unroll
        for (int ks = 0; ks < 4; ks++) {
            const uint32_t aOff = (uint32_t)(ks * 16) * 2;
            const uint32_t bOff = (uint32_t)(ks * 16) * HS_S * 2;
            uint32_t a0, a1, a2, a3, b0, b1, b2, b3;
            ldsm_x4(a0, a1, a2, a3, aAddr + aOff);
            ldsm_x4t(b0, b1, b2, b3, bAddr + bOff);
            mma16816(acc0, a0, a1, a2, a3, b0, b1);
            mma16816(acc1, a0, a1, a2, a3, b2, b3);
        }
        __syncthreads();
    }

    // row sums -> inv
#pragma unroll
    for (int rr = 0; rr < 4; rr++) {
        float sum = sum_r[rr];
#pragma unroll
        for (int o = 16; o; o >>= 1) sum += __shfl_xor_sync(0xffffffffu, sum, o);
        if (lane == 0) inv[warp * 4 + rr] = 1.0f / sum;
    }
    __syncthreads();

    // Epilogue: normalize + leaky_relu(0.01) + store
    const int gid = lane >> 2;
    const int tg  = lane & 3;
    const int rA  = mtile * 16 + gid;
    const int rB  = rA + 8;
    const float invA = inv[rA];
    const float invB = inv[rB];

#pragma unroll
    for (int nt = 0; nt < 2; nt++) {
        float* acc = nt ? acc1 : acc0;
        int col = (ntg0 + nt) * 8 + tg * 2;
        float v;
        float2 oA, oB;
        v = acc[0] * invA; oA.x = v > 0.f ? v : 0.01f * v;
        v = acc[1] * invA; oA.y = v > 0.f ? v : 0.01f * v;
        v = acc[2] * invB; oB.x = v > 0.f ? v : 0.01f * v;
        v = acc[3] * invB; oB.y = v > 0.f ? v : 0.01f * v;
        *(float2*)(out + ((size_t)b * N_ + r0 + rA) * FOUT + col) = oA;
        *(float2*)(out + ((size_t)b * N_ + r0 + rB) * FOUT + col) = oB;
    }
}

// ---------------------------------------------------------------------------
extern "C" void kernel_launch(void* const* d_in, const int* in_sizes, int n_in,
                              void* d_out, int out_size)
{
    const float* X   = (const float*)d_in[0];
    const int*   adj = (const int*)  d_in[1];
    const float* W   = (const float*)d_in[2];
    const float* a   = (const float*)d_in[3];
    float* out = (float*)d_out;

    size_t smA = (size_t)(64 * 68 + 128 * 64) * sizeof(float);   // ~50 KB
    cudaFuncSetAttribute(gemm1_kernel, cudaFuncAttributeMaxDynamicSharedMemorySize, (int)smA);
    gemm1_kernel<<<(B_ * N_) / 64, 256, smA>>>(X, W, a);

    size_t smB = (512 + 32 + 8) * sizeof(float)
               + (size_t)(32 * ATT_S + 64 * HS_S) * sizeof(__half);   // ~16 KB
    cudaFuncSetAttribute(attn_kernel, cudaFuncAttributeMaxDynamicSharedMemorySize, (int)smB);
    attn_kernel<<<dim3(N_ / 32, B_), 256, smB>>>(adj, out);
}

// round 6
// speedup vs baseline: 1.5210x; 1.2425x over previous
#include <cuda_runtime.h>
#include <cuda_fp16.h>
#include <cstdint>

#define B_   128
#define N_   512
#define FIN  128
#define FOUT 64

// Scratch (allocation-free rule: __device__ globals)
__device__ __half g_hh[B_ * N_ * FOUT];   // h fp16, row-major [row][f]
__device__ float  g_s[B_ * N_];
__device__ float  g_t[B_ * N_];

// ---------------------------------------------------------------------------
// PTX helpers
// ---------------------------------------------------------------------------
__device__ __forceinline__ uint32_t smem_u32(const void* p) {
    return (uint32_t)__cvta_generic_to_shared(p);
}
__device__ __forceinline__ void ldsm_x4(uint32_t& r0, uint32_t& r1, uint32_t& r2, uint32_t& r3, uint32_t addr) {
    asm volatile("ldmatrix.sync.aligned.m8n8.x4.shared.b16 {%0,%1,%2,%3}, [%4];\n"
                 : "=r"(r0), "=r"(r1), "=r"(r2), "=r"(r3) : "r"(addr));
}
__device__ __forceinline__ void ldsm_x4t(uint32_t& r0, uint32_t& r1, uint32_t& r2, uint32_t& r3, uint32_t addr) {
    asm volatile("ldmatrix.sync.aligned.m8n8.x4.trans.shared.b16 {%0,%1,%2,%3}, [%4];\n"
                 : "=r"(r0), "=r"(r1), "=r"(r2), "=r"(r3) : "r"(addr));
}
__device__ __forceinline__ void mma16816(float* d, uint32_t a0, uint32_t a1, uint32_t a2, uint32_t a3,
                                         uint32_t b0, uint32_t b1) {
    asm volatile("mma.sync.aligned.m16n8k16.row.col.f32.f16.f16.f32 "
                 "{%0,%1,%2,%3},{%4,%5,%6,%7},{%8,%9},{%0,%1,%2,%3};\n"
                 : "+f"(d[0]), "+f"(d[1]), "+f"(d[2]), "+f"(d[3])
                 : "r"(a0), "r"(a1), "r"(a2), "r"(a3), "r"(b0), "r"(b1));
}
__device__ __forceinline__ void cp_async16(uint32_t saddr, const void* gptr) {
    asm volatile("cp.async.cg.shared.global [%0], [%1], 16;\n" :: "r"(saddr), "l"(gptr));
}
#define CP_COMMIT() asm volatile("cp.async.commit_group;\n" ::: "memory")
#define CP_WAIT0()  asm volatile("cp.async.wait_group 0;\n" ::: "memory")

// ---------------------------------------------------------------------------
// Kernel A: h = X @ W  (M=65536, K=128, N=64), K split in 2 halves for occ.
//   writes fp16 h, and fused s = h.a_src, t = h.a_dst
// ---------------------------------------------------------------------------
__global__ void __launch_bounds__(256) gemm1_kernel(
    const float* __restrict__ X, const float* __restrict__ W,
    const float* __restrict__ a)
{
    extern __shared__ float sm[];
    float* Xs = sm;               // [64][68]
    float* Ws = sm + 64 * 68;     // [128][64]

    const int tid = threadIdx.x;
    const int m0  = blockIdx.x * 64;

#pragma unroll
    for (int p = 0; p < 8; p++) {
        int u  = p * 256 + tid;
        int k  = u >> 4;
        int c4 = (u & 15) * 4;
        *(float4*)(Ws + k * 64 + c4) = *(const float4*)(W + k * 64 + c4);
    }

    const int tx = tid & 15;
    const int ty = tid >> 4;
    float acc[4][4] = {};

#pragma unroll
    for (int kh = 0; kh < 2; kh++) {
#pragma unroll
        for (int p = 0; p < 4; p++) {
            int u  = p * 256 + tid;
            int r  = u >> 4;
            int k4 = (u & 15) * 4;
            *(float4*)(Xs + r * 68 + k4) =
                *(const float4*)(X + (size_t)(m0 + r) * FIN + kh * 64 + k4);
        }
        __syncthreads();

#pragma unroll 8
        for (int k = 0; k < 64; k++) {
            float4 wv = *(const float4*)(Ws + (kh * 64 + k) * 64 + tx * 4);
            float x0 = Xs[(ty * 4 + 0) * 68 + k];
            float x1 = Xs[(ty * 4 + 1) * 68 + k];
            float x2 = Xs[(ty * 4 + 2) * 68 + k];
            float x3 = Xs[(ty * 4 + 3) * 68 + k];
            acc[0][0] += x0 * wv.x; acc[0][1] += x0 * wv.y; acc[0][2] += x0 * wv.z; acc[0][3] += x0 * wv.w;
            acc[1][0] += x1 * wv.x; acc[1][1] += x1 * wv.y; acc[1][2] += x1 * wv.z; acc[1][3] += x1 * wv.w;
            acc[2][0] += x2 * wv.x; acc[2][1] += x2 * wv.y; acc[2][2] += x2 * wv.z; acc[2][3] += x2 * wv.w;
            acc[3][0] += x3 * wv.x; acc[3][1] += x3 * wv.y; acc[3][2] += x3 * wv.z; acc[3][3] += x3 * wv.w;
        }
        __syncthreads();
    }

    float as[4], ad[4];
#pragma unroll
    for (int c = 0; c < 4; c++) {
        as[c] = __ldg(a + tx * 4 + c);
        ad[c] = __ldg(a + 64 + tx * 4 + c);
    }

#pragma unroll
    for (int i = 0; i < 4; i++) {
        size_t row = (size_t)(m0 + ty * 4 + i);
        __half hv[4];
#pragma unroll
        for (int c = 0; c < 4; c++) hv[c] = __float2half(acc[i][c]);
        *(uint2*)(g_hh + row * FOUT + tx * 4) = *(uint2*)hv;

        float sp = acc[i][0] * as[0] + acc[i][1] * as[1] + acc[i][2] * as[2] + acc[i][3] * as[3];
        float tp = acc[i][0] * ad[0] + acc[i][1] * ad[1] + acc[i][2] * ad[2] + acc[i][3] * ad[3];
#pragma unroll
        for (int o = 8; o; o >>= 1) {
            sp += __shfl_xor_sync(0xffffffffu, sp, o);
            tp += __shfl_xor_sync(0xffffffffu, tp, o);
        }
        if (tx == 0) { g_s[row] = sp; g_t[row] = tp; }
    }
}

// ---------------------------------------------------------------------------
// Kernel B: chunked masked-softmax + tensor-core att@h, software-pipelined:
//   adj reg-prefetch (chunk c+1 LDG issued before phase-1 of c)
//   hs double-buffered cp.async (loads fly under phase-1 + MMA)
//   attC double-buffered (1 barrier per chunk)
// ---------------------------------------------------------------------------
#define ATT_S 72    // fp16 stride (64 + 8 pad)
#define HS_S  72

__global__ void __launch_bounds__(256, 4) attn_kernel(
    const int* __restrict__ adj, float* __restrict__ out)
{
    extern __shared__ char smraw[];
    float* t_sh = (float*)smraw;                 // 512
    float* inv  = t_sh + 512;                    // 32
    float* wmax = inv + 32;                      // 8
    __half* attC = (__half*)(wmax + 8);          // 2 x 32 x 72
    __half* hsC  = attC + 2 * 32 * ATT_S;        // 2 x 64 x 72

    const int b    = blockIdx.y;
    const int r0   = blockIdx.x * 32;
    const int tid  = threadIdx.x;
    const int warp = tid >> 5;
    const int lane = tid & 31;

    // hs cp.async per-thread targets (2 x 16B per chunk)
    const int ld_row = tid >> 3;          // 0..31 (+32 on rep 2)
    const int ld_off = (tid & 7) * 8;     // halves
    const __half* hb = g_hh + (size_t)b * N_ * FOUT;
    const uint32_t hsBase = smem_u32(hsC);

    // prologue: stream hs chunk 0 into buf 0
    {
        cp_async16(hsBase + (uint32_t)((ld_row)      * HS_S + ld_off) * 2, hb + (size_t)(ld_row)      * FOUT + ld_off);
        cp_async16(hsBase + (uint32_t)((ld_row + 32) * HS_S + ld_off) * 2, hb + (size_t)(ld_row + 32) * FOUT + ld_off);
        CP_COMMIT();
    }

    float t0 = g_t[b * N_ + tid];
    float t1 = g_t[b * N_ + tid + 256];
    t_sh[tid]       = t0;
    t_sh[tid + 256] = t1;

    float m2 = fmaxf(t0, t1);
#pragma unroll
    for (int o = 16; o; o >>= 1) m2 = fmaxf(m2, __shfl_xor_sync(0xffffffffu, m2, o));
    if (lane == 0) wmax[warp] = m2;
    __syncthreads();
    const float maxT = fmaxf(fmaxf(fmaxf(wmax[0], wmax[1]), fmaxf(wmax[2], wmax[3])),
                             fmaxf(fmaxf(wmax[4], wmax[5]), fmaxf(wmax[6], wmax[7])));

    // per-row constants (warp owns local rows warp*4 .. +3)
    float s_r[4], mx_r[4], sum_r[4];
#pragma unroll
    for (int rr = 0; rr < 4; rr++) {
        int grow = r0 + warp * 4 + rr;
        float s  = g_s[b * N_ + grow];
        float pm = s + maxT;
        s_r[rr]  = s;
        mx_r[rr] = pm > 0.f ? pm : 0.2f * pm;
        sum_r[rr] = 0.f;
    }

    // fragment addressing
    const int mtile  = warp >> 2;
    const int ntg0   = (warp & 3) * 2;
    const int lrow16 = lane & 15;
    const int lhalf  = lane >> 4;
    const uint32_t aBase = smem_u32(attC + (mtile * 16 + lrow16) * ATT_S + lhalf * 8);
    const uint32_t bBase = smem_u32(hsC + lrow16 * HS_S + (ntg0 + lhalf) * 8);
    const uint32_t attBufB = (uint32_t)(32 * ATT_S) * 2;   // bytes per att buffer
    const uint32_t hsBufB  = (uint32_t)(64 * HS_S) * 2;    // bytes per hs buffer

    float acc0[4] = {0.f, 0.f, 0.f, 0.f};
    float acc1[4] = {0.f, 0.f, 0.f, 0.f};

    const int* adjB = adj + ((size_t)b * N_ + r0) * N_;

    // adj prefetch for chunk 0
    int2 avc[4], avn[4];
#pragma unroll
    for (int rr = 0; rr < 4; rr++)
        avc[rr] = *(const int2*)(adjB + (size_t)(warp * 4 + rr) * N_ + lane * 2);

    for (int c = 0; c < 8; c++) {
        const int k0  = c * 64;
        const int buf = c & 1;

        // issue adj prefetch for chunk c+1
        if (c < 7) {
#pragma unroll
            for (int rr = 0; rr < 4; rr++)
                avn[rr] = *(const int2*)(adjB + (size_t)(warp * 4 + rr) * N_ + k0 + 64 + lane * 2);
        }

        // phase-1: weights for 32 rows x 64 cols -> attC[buf]
        __half* attW = attC + buf * 32 * ATT_S;
#pragma unroll
        for (int rr = 0; rr < 4; rr++) {
            int r = warp * 4 + rr;
            float2 tv = *(const float2*)(t_sh + k0 + lane * 2);
            float e0 = s_r[rr] + tv.x; e0 = e0 > 0.f ? e0 : 0.2f * e0;
            float e1 = s_r[rr] + tv.y; e1 = e1 > 0.f ? e1 : 0.2f * e1;
            float w0 = avc[rr].x > 0 ? __expf(e0 - mx_r[rr]) : 0.f;
            float w1 = avc[rr].y > 0 ? __expf(e1 - mx_r[rr]) : 0.f;
            sum_r[rr] += w0 + w1;
            __half2 p = __floats2half2_rn(w0, w1);
            *(uint32_t*)(attW + r * ATT_S + lane * 2) = *(uint32_t*)&p;
        }

        CP_WAIT0();            // hs[c] landed (issued last iteration)
        __syncthreads();       // attC[buf] + hs[buf] visible to all

        // stream hs chunk c+1 into the other buffer (safe: all passed barrier)
        if (c < 7) {
            const __half* hn = hb + (size_t)(k0 + 64) * FOUT;
            uint32_t dst = hsBase + (1 - buf) * hsBufB;
            cp_async16(dst + (uint32_t)((ld_row)      * HS_S + ld_off) * 2, hn + (size_t)(ld_row)      * FOUT + ld_off);
            cp_async16(dst + (uint32_t)((ld_row + 32) * HS_S + ld_off) * 2, hn + (size_t)(ld_row + 32) * FOUT + ld_off);
            CP_COMMIT();
        }

        // MMA: C[32,64] += attC[buf] @ hsC[buf]
        const uint32_t aA = aBase + buf * attBufB;
        const uint32_t bA = bBase + buf * hsBufB;
#pragma unroll
        for (int ks = 0; ks < 4; ks++) {
            const uint32_t aOff = (uint32_t)(ks * 16) * 2;
            const uint32_t bOff = (uint32_t)(ks * 16) * HS_S * 2;
            uint32_t a0, a1, a2, a3, b0, b1, b2, b3;
            ldsm_x4(a0, a1, a2, a3, aA + aOff);
            ldsm_x4t(b0, b1, b2, b3, bA + bOff);
            mma16816(acc0, a0, a1, a2, a3, b0, b1);
            mma16816(acc1, a0, a1, a2, a3, b2, b3);
        }

#pragma unroll
        for (int rr = 0; rr < 4; rr++) avc[rr] = avn[rr];
    }

    // row sums -> inv
#pragma unroll
    for (int rr = 0; rr < 4; rr++) {
        float sum = sum_r[rr];
#pragma unroll
        for (int o = 16; o; o >>= 1) sum += __shfl_xor_sync(0xffffffffu, sum, o);
        if (lane == 0) inv[warp * 4 + rr] = 1.0f / sum;
    }
    __syncthreads();

    // epilogue: normalize + leaky_relu(0.01) + store
    const int gid = lane >> 2;
    const int tg  = lane & 3;
    const int rA  = mtile * 16 + gid;
    const int rB  = rA + 8;
    const float invA = inv[rA];
    const float invB = inv[rB];

#pragma unroll
    for (int nt = 0; nt < 2; nt++) {
        float* acc = nt ? acc1 : acc0;
        int col = (ntg0 + nt) * 8 + tg * 2;
        float v;
        float2 oA, oB;
        v = acc[0] * invA; oA.x = v > 0.f ? v : 0.01f * v;
        v = acc[1] * invA; oA.y = v > 0.f ? v : 0.01f * v;
        v = acc[2] * invB; oB.x = v > 0.f ? v : 0.01f * v;
        v = acc[3] * invB; oB.y = v > 0.f ? v : 0.01f * v;
        *(float2*)(out + ((size_t)b * N_ + r0 + rA) * FOUT + col) = oA;
        *(float2*)(out + ((size_t)b * N_ + r0 + rB) * FOUT + col) = oB;
    }
}

// ---------------------------------------------------------------------------
extern "C" void kernel_launch(void* const* d_in, const int* in_sizes, int n_in,
                              void* d_out, int out_size)
{
    const float* X   = (const float*)d_in[0];
    const int*   adj = (const int*)  d_in[1];
    const float* W   = (const float*)d_in[2];
    const float* a   = (const float*)d_in[3];
    float* out = (float*)d_out;

    size_t smA = (size_t)(64 * 68 + 128 * 64) * sizeof(float);   // ~50 KB
    cudaFuncSetAttribute(gemm1_kernel, cudaFuncAttributeMaxDynamicSharedMemorySize, (int)smA);
    gemm1_kernel<<<(B_ * N_) / 64, 256, smA>>>(X, W, a);

    size_t smB = (512 + 32 + 8) * sizeof(float)
               + (size_t)(2 * 32 * ATT_S + 2 * 64 * HS_S) * sizeof(__half);  // ~29 KB
    cudaFuncSetAttribute(attn_kernel, cudaFuncAttributeMaxDynamicSharedMemorySize, (int)smB);
    attn_kernel<<<dim3(N_ / 32, B_), 256, smB>>>(adj, out);
}